// round 15
// baseline (speedup 1.0000x reference)
#include <cuda_runtime.h>

#define NACC 352          // 32 G + 320 M (before squares)
#define PI_F 3.14159265358979323846f
#define C6   (PI_F / 6.0f)
#define C4   (PI_F / 4.0f)

// scratch
__device__ float  g_feat[2048 * NACC];      // final per-atom features
__device__ float4 g_w1p4[160 * 64];         // (w[f0],wsq[f0],w[f1],wsq[f1])

__device__ __forceinline__ float fast_tanh(float x) {
    float y;
    asm("tanh.approx.f32 %0, %1;" : "=f"(y) : "f"(x));
    return y;
}
__device__ __forceinline__ float fast_sigmoid(float x) {
    return 0.5f * fast_tanh(0.5f * x) + 0.5f;
}

// -------------------------------------------------------------------------
// Kernel 1: descriptors + W1 packing (unchanged from round 14).
// Blocks >= N/2 pack W1 and exit.  Feat blocks: 2 atoms x 4 j-quarter
// warps; ballot-compacted survivor records in warp slabs, broadcast-LDS
// accumulate into registers, block-reduce quarter partials (deterministic
// fixed order) -> one g_feat write per atom.
// -------------------------------------------------------------------------
__global__ __launch_bounds__(256) void feat_kernel(
    const float* __restrict__ pos,
    const float* __restrict__ spec,
    const float* __restrict__ kn_rad,
    const float* __restrict__ kn_ang,
    const float* __restrict__ rbf_w,
    const float* __restrict__ rbf_b,
    const float* __restrict__ rbf_aw,
    const float* __restrict__ rbf_ab,
    const float* __restrict__ W1,
    int N)
{
    const int tid = threadIdx.x;

    if (blockIdx.x >= (unsigned)(N / 2)) {                 // pack blocks
        int idx = (blockIdx.x - N / 2) * 256 + tid;        // < 10240
        int q = idx >> 6;
        int h = idx & 63;
        int f0 = 32 + 2 * q;
        g_w1p4[idx] = make_float4(W1[f0 * 64 + h],
                                  W1[(f0 + 320) * 64 + h],
                                  W1[(f0 + 1) * 64 + h],
                                  W1[(f0 + 321) * 64 + h]);
        return;
    }

    const int wid  = tid >> 5;
    const int lane = tid & 31;
    const int ia   = wid >> 2;               // 0/1: local atom
    const int i    = blockIdx.x * 2 + ia;    // atom
    const int quar = wid & 3;                // j-quarter
    const int myl  = lane >> 2;
    const int mye  = lane & 3;

    __shared__ float4 spos[2048];            // 32 KB
    __shared__ float  rec[8][32 * 12];       // 12 KB warp slabs / red buffer

    for (int idx = tid; idx < N; idx += 256)
        spos[idx] = make_float4(pos[3 * idx + 0], pos[3 * idx + 1],
                                pos[3 * idx + 2], 0.0f);
    __syncthreads();

    const float crk = C6 * (float)(myl + 1) * kn_rad[myl];
    const float cak = C4 * (float)(myl + 1) * kn_ang[myl];
    const float wr = rbf_w[myl],  br = rbf_b[myl];
    const float wa = rbf_aw[myl], ba = rbf_ab[myl];

    const float4 pi = spos[i];
    const float4 si = __ldg(((const float4*)spec) + i);
    const float sie = (mye == 0) ? si.x : (mye == 1) ? si.y
                    : (mye == 2) ? si.z : si.w;

    float gacc = 0.0f;
    float macc[10];
    #pragma unroll
    for (int p = 0; p < 10; p++) macc[p] = 0.0f;

    float* slab = &rec[wid][0];
    const unsigned ltm = (1u << lane) - 1u;
    const int jbeg = quar * (N >> 2);
    const int jend = jbeg + (N >> 2);

    for (int j0 = jbeg; j0 < jend; j0 += 32) {
        int j = j0 + lane;
        float4 pj = spos[j];
        float rx = pi.x - pj.x;
        float ry = pi.y - pj.y;
        float rz = pi.z - pj.z;
        float d2 = fmaf(rx, rx, fmaf(ry, ry, rz * rz)) + 1e-16f;
        float inv = rsqrtf(d2);
        float rn = d2 * inv;
        bool pr = (j != i) && (rn <= 6.0f);
        bool pa = pr && (rn <= 4.0f);
        unsigned mr = __ballot_sync(0xffffffffu, pr);
        unsigned ma = __ballot_sync(0xffffffffu, pa);
        int cnt_a = __popc(ma);
        int cnt   = __popc(mr);

        if (pr) {
            int slot = pa ? __popc(ma & ltm)
                          : cnt_a + __popc((mr & ~ma) & ltm);
            float4 sj = __ldg(((const float4*)spec) + j);
            float* rp = slab + slot * 12;
            ((float4*)rp)[0] = make_float4(rx * inv, ry * inv, rz * inv, rn);
            ((float4*)rp)[1] = make_float4(inv, sj.x, sj.y, sj.z);
            rp[8] = sj.w;
        }
        __syncwarp();

        for (int q = 0; q < cnt_a; q++) {
            const float* rp = slab + q * 12;
            float4 u   = ((const float4*)rp)[0];
            float  riv = rp[4];
            float  spj = rp[5 + mye];
            float  srn = u.w;

            float gr = 1.0f, ga = 1.0f;
            if (srn <= 1.5f) {                       // warp-uniform branch
                gr = fast_sigmoid(fmaf(srn, wr, br));
                ga = fast_sigmoid(fmaf(srn, wa, ba));
            }
            float fc   = 0.5f * (__cosf(C6 * srn) + 1.0f);
            float radl = __sinf(crk * srn) * (riv * fc) * gr;
            gacc = fmaf(radl, spj, gacc);

            float fca = 0.5f * (__cosf(C4 * srn) + 1.0f);
            float ral = __sinf(cak * srn) * (riv * fca) * ga;
            float w  = ral * spj;
            float wx = w * u.x, wy = w * u.y, wz = w * u.z;
            macc[0] += w;
            macc[1] += wz;
            macc[2] += wy;
            macc[3] += wx;
            macc[4] = fmaf(wz, u.z, macc[4]);
            macc[5] = fmaf(wz, u.y, macc[5]);
            macc[6] = fmaf(wy, u.y, macc[6]);
            macc[7] = fmaf(wz, u.x, macc[7]);
            macc[8] = fmaf(wy, u.x, macc[8]);
            macc[9] = fmaf(wx, u.x, macc[9]);
        }
        for (int q = cnt_a; q < cnt; q++) {
            const float* rp = slab + q * 12;
            float srn = rp[3];
            float riv = rp[4];
            float spj = rp[5 + mye];
            float gr = 1.0f;
            if (srn <= 1.5f)                         // warp-uniform branch
                gr = fast_sigmoid(fmaf(srn, wr, br));
            float fc   = 0.5f * (__cosf(C6 * srn) + 1.0f);
            float radl = __sinf(crk * srn) * (riv * fc) * gr;
            gacc = fmaf(radl, spj, gacc);
        }
        __syncwarp();
    }

    // ---- block reduction of the 4 quarter-partials per atom ----
    __syncthreads();                         // slabs no longer needed
    float* red = &rec[0][0];                 // [atom2][quar][352]
    {
        float* rb = red + (ia * 4 + quar) * NACC;
        rb[myl * 4 + mye] = gacc * sie;
        #pragma unroll
        for (int p = 0; p < 10; p++)
            rb[32 + myl * 40 + p * 4 + mye] = macc[p] * sie;
    }
    __syncthreads();
    for (int idx = tid; idx < 2 * NACC; idx += 256) {
        int a = idx / NACC;
        int f = idx - a * NACC;
        const float* rb = red + a * 4 * NACC;
        float v = (rb[f] + rb[NACC + f])
                + (rb[2 * NACC + f] + rb[3 * NACC + f]);
        g_feat[(blockIdx.x * 2 + a) * NACC + f] = v;
    }
}

// -------------------------------------------------------------------------
// Kernel 2: fused MLP (672 -> 64 tanh -> 64 tanh -> 1).  4 atoms/block,
// grid 512 (~28 warps/SM: latency-robust), 256 threads, ONE atom per
// thread (h = tid&63, grp = tid>>6).  Layer-1 M-weights via packed float4
// (1 LDG.128 = 2 rows x (linear, square)); two accumulators for FMA ILP.
// Weight re-reads across blocks on the same SM hit L1 (persists in-launch).
// -------------------------------------------------------------------------
__global__ __launch_bounds__(256) void mlp_kernel(
    const float* __restrict__ W1, const float* __restrict__ b1,
    const float* __restrict__ W2, const float* __restrict__ b2,
    const float* __restrict__ W3, const float* __restrict__ b3,
    float* __restrict__ out, int N)
{
    const int i0   = blockIdx.x * 4;
    const int tid  = threadIdx.x;
    const int h    = tid & 63;
    const int grp  = tid >> 6;          // 0..3 -> atom i0+grp
    const int wid  = tid >> 5;

    __shared__ float sfr[NACC * 4];     // [f][a]  5.5 KB
    __shared__ float sh1[64 * 4];
    __shared__ float part[8];

    for (int idx = tid; idx < NACC * 4; idx += 256) {
        int aa = idx >> 31; (void)aa;
        int a = idx / NACC;
        int f = idx - a * NACC;
        sfr[f * 4 + a] = g_feat[(i0 + a) * NACC + f];
    }
    __syncthreads();

    float accA = 0.0f, accB = 0.0f;
    // G rows
    #pragma unroll 8
    for (int f = 0; f < 32; f += 2) {
        accA = fmaf(sfr[f * 4 + grp],       __ldg(&W1[f * 64 + h]),       accA);
        accB = fmaf(sfr[(f + 1) * 4 + grp], __ldg(&W1[(f + 1) * 64 + h]), accB);
    }
    // M row pairs, packed weights; accA/accB give two independent chains
    #pragma unroll 8
    for (int q = 0; q < 160; q++) {
        float4 wv = __ldg(&g_w1p4[q * 64 + h]);
        float v0 = sfr[(32 + 2 * q) * 4 + grp];
        float v1 = sfr[(33 + 2 * q) * 4 + grp];
        accA = fmaf(v0, fmaf(v0, wv.y, wv.x), accA);
        accB = fmaf(v1, fmaf(v1, wv.w, wv.z), accB);
    }
    sh1[h * 4 + grp] = fast_tanh(accA + accB + __ldg(&b1[h]));
    __syncthreads();

    float s0 = __ldg(&b2[h]);
    #pragma unroll 8
    for (int k = 0; k < 64; k++)
        s0 = fmaf(sh1[k * 4 + grp], __ldg(&W2[k * 64 + h]), s0);

    float c0 = fast_tanh(s0) * __ldg(&W3[h]);
    #pragma unroll
    for (int o = 16; o > 0; o >>= 1)
        c0 += __shfl_down_sync(0xffffffffu, c0, o);
    if ((tid & 31) == 0) part[wid] = c0;
    __syncthreads();
    if (tid < 4)
        out[i0 + tid] = part[2 * tid] + part[2 * tid + 1] + b3[0];
}

// -------------------------------------------------------------------------
extern "C" void kernel_launch(void* const* d_in, const int* in_sizes, int n_in,
                              void* d_out, int out_size)
{
    const float* pos    = (const float*)d_in[0];
    const float* spec   = (const float*)d_in[1];
    const float* kn_rad = (const float*)d_in[2];
    const float* kn_ang = (const float*)d_in[3];
    const float* rbf_w  = (const float*)d_in[4];
    const float* rbf_b  = (const float*)d_in[5];
    const float* rbf_aw = (const float*)d_in[6];
    const float* rbf_ab = (const float*)d_in[7];
    const float* W1     = (const float*)d_in[8];
    const float* b1     = (const float*)d_in[9];
    const float* W2     = (const float*)d_in[10];
    const float* b2     = (const float*)d_in[11];
    const float* W3     = (const float*)d_in[12];
    const float* b3     = (const float*)d_in[13];

    int N = in_sizes[0] / 3;   // 2048

    feat_kernel<<<N / 2 + 40, 256>>>(pos, spec, kn_rad, kn_ang,
                                     rbf_w, rbf_b, rbf_aw, rbf_ab,
                                     W1, N);
    mlp_kernel<<<N / 4, 256>>>(W1, b1, W2, b2, W3, b3, (float*)d_out, N);
}